// round 2
// baseline (speedup 1.0000x reference)
#include <cuda_runtime.h>
#include <cstdint>
#include <cstddef>

// ---------------- problem constants ----------------
#define BSZ   2
#define LSEQ  2048
#define DIMV  472          // DIM == V
#define ED    944
#define NST   16
#define RK    30
#define NDEPTH 8
#define MROWS (BSZ*LSEQ)   // 4096
#define XZW   (2*ED)       // 1888
#define DBLW  (RK + 2*NST) // 62

// ---------------- scratch (device globals: allocation-free) ----------------
__device__ float g_h[(size_t)MROWS*DIMV];            //  7.7 MB residual stream
__device__ float g_xz[(size_t)MROWS*XZW];            // 30.9 MB
__device__ float g_xc[2][(size_t)MROWS*ED];          // 31 MB  (fwd/bwd conv out)
__device__ float g_dbl[2][(size_t)MROWS*DBLW];       //  2 MB
__device__ float g_delta[2][(size_t)MROWS*ED];       // 31 MB
__device__ float g_y[(size_t)MROWS*ED];              // 15.5 MB (summed scan output)

// ---------------- patch embed ----------------
__global__ void patch_kernel(const float* __restrict__ x,
                             const float* __restrict__ pw,
                             const float* __restrict__ pb)
{
    int i = blockIdx.x*blockDim.x + threadIdx.x;
    if (i >= MROWS*DIMV) return;
    int m = i / DIMV, v = i - m*DIMV;
    const float* xr = x + (size_t)m*9;
    const float* wr = pw + (size_t)v*9;
    float s = pb[v];
#pragma unroll
    for (int k = 0; k < 9; k++) s = fmaf(xr[k], wr[k], s);
    g_h[i] = s;
}

// ---------------- big SGEMM: C[M,N] = A[M,K] * W[N,K]^T (+C) ----------------
// M must be a multiple of 128 (always 4096 here). N, K arbitrary (guarded).
__device__ __forceinline__ float4 ld4_guard(const float* p, int k0, int K)
{
    float4 v = make_float4(0.f, 0.f, 0.f, 0.f);
    if (k0 + 3 < K) v = *(const float4*)p;
    else if (k0 < K) {
        v.x = p[0];
        if (k0 + 1 < K) v.y = p[1];
        if (k0 + 2 < K) v.z = p[2];
    }
    return v;
}

__global__ __launch_bounds__(256)
void sgemm_nt(const float* __restrict__ A, const float* __restrict__ W,
              float* __restrict__ C, int N, int K, int accum)
{
    __shared__ float As[2][16][128];
    __shared__ float Bs[2][16][128];
    const int tid = threadIdx.x;
    const int bm  = blockIdx.y * 128;
    const int bn  = blockIdx.x * 128;
    const int lr  = tid >> 2;          // 0..63
    const int lc  = (tid & 3) << 2;    // 0,4,8,12
    const int tx  = tid & 15, ty = tid >> 4;

    float acc[8][8];
#pragma unroll
    for (int i = 0; i < 8; i++)
#pragma unroll
        for (int j = 0; j < 8; j++) acc[i][j] = 0.f;

    const int nkt = (K + 15) >> 4;
    float4 ra[2], rb[2];

    // prologue: tile 0
    {
        int k0 = lc;
#pragma unroll
        for (int i = 0; i < 2; i++) {
            int row = lr + i*64;
            ra[i] = ld4_guard(A + (size_t)(bm+row)*K + k0, k0, K);
            int n = bn + row;
            rb[i] = (n < N) ? ld4_guard(W + (size_t)n*K + k0, k0, K)
                            : make_float4(0.f,0.f,0.f,0.f);
        }
#pragma unroll
        for (int i = 0; i < 2; i++) {
            int row = lr + i*64;
            As[0][lc+0][row] = ra[i].x; As[0][lc+1][row] = ra[i].y;
            As[0][lc+2][row] = ra[i].z; As[0][lc+3][row] = ra[i].w;
            Bs[0][lc+0][row] = rb[i].x; Bs[0][lc+1][row] = rb[i].y;
            Bs[0][lc+2][row] = rb[i].z; Bs[0][lc+3][row] = rb[i].w;
        }
    }
    __syncthreads();

    for (int kt = 0; kt < nkt; kt++) {
        int buf = kt & 1;
        if (kt + 1 < nkt) {
            int k0 = (kt+1)*16 + lc;
#pragma unroll
            for (int i = 0; i < 2; i++) {
                int row = lr + i*64;
                ra[i] = ld4_guard(A + (size_t)(bm+row)*K + k0, k0, K);
                int n = bn + row;
                rb[i] = (n < N) ? ld4_guard(W + (size_t)n*K + k0, k0, K)
                                : make_float4(0.f,0.f,0.f,0.f);
            }
        }
#pragma unroll
        for (int k = 0; k < 16; k++) {
            float a[8], b[8];
            *(float4*)&a[0] = *(const float4*)&As[buf][k][ty*8];
            *(float4*)&a[4] = *(const float4*)&As[buf][k][ty*8+4];
            *(float4*)&b[0] = *(const float4*)&Bs[buf][k][tx*8];
            *(float4*)&b[4] = *(const float4*)&Bs[buf][k][tx*8+4];
#pragma unroll
            for (int i = 0; i < 8; i++)
#pragma unroll
                for (int j = 0; j < 8; j++)
                    acc[i][j] = fmaf(a[i], b[j], acc[i][j]);
        }
        if (kt + 1 < nkt) {
            int nb = buf ^ 1;
#pragma unroll
            for (int i = 0; i < 2; i++) {
                int row = lr + i*64;
                As[nb][lc+0][row] = ra[i].x; As[nb][lc+1][row] = ra[i].y;
                As[nb][lc+2][row] = ra[i].z; As[nb][lc+3][row] = ra[i].w;
                Bs[nb][lc+0][row] = rb[i].x; Bs[nb][lc+1][row] = rb[i].y;
                Bs[nb][lc+2][row] = rb[i].z; Bs[nb][lc+3][row] = rb[i].w;
            }
        }
        __syncthreads();
    }

#pragma unroll
    for (int i = 0; i < 8; i++) {
        size_t row = (size_t)(bm + ty*8 + i);
        float* crow = C + row*(size_t)N;
#pragma unroll
        for (int j = 0; j < 8; j += 4) {
            int col = bn + tx*8 + j;
            if (col + 3 < N) {
                float4 v = make_float4(acc[i][j], acc[i][j+1], acc[i][j+2], acc[i][j+3]);
                if (accum) {
                    float4 o = *(const float4*)&crow[col];
                    v.x += o.x; v.y += o.y; v.z += o.z; v.w += o.w;
                }
                *(float4*)&crow[col] = v;
            } else {
#pragma unroll
                for (int jj = 0; jj < 4; jj++) {
                    int c2 = col + jj;
                    if (c2 < N) {
                        float v = acc[i][j+jj];
                        if (accum) v += crow[c2];
                        crow[c2] = v;
                    }
                }
            }
        }
    }
}

// ---------------- depthwise causal/anticausal conv + SiLU ----------------
__global__ void conv_silu_kernel(const float* __restrict__ cw,
                                 const float* __restrict__ cb)
{
    int dir = blockIdx.y;
    int i = blockIdx.x*blockDim.x + threadIdx.x;
    if (i >= MROWS*ED) return;
    int m = i / ED, e = i - m*ED;
    int t = m & (LSEQ-1);
    float w0 = cw[e*4+0], w1 = cw[e*4+1], w2 = cw[e*4+2], w3 = cw[e*4+3];
    const float* xr = g_xz;  // xi = cols [0,ED)
    float s = xr[(size_t)m*XZW + e] * w3;
    if (dir == 0) {
        if (t >= 1) s = fmaf(xr[(size_t)(m-1)*XZW + e], w2, s);
        if (t >= 2) s = fmaf(xr[(size_t)(m-2)*XZW + e], w1, s);
        if (t >= 3) s = fmaf(xr[(size_t)(m-3)*XZW + e], w0, s);
    } else {
        if (t+1 < LSEQ) s = fmaf(xr[(size_t)(m+1)*XZW + e], w2, s);
        if (t+2 < LSEQ) s = fmaf(xr[(size_t)(m+2)*XZW + e], w1, s);
        if (t+3 < LSEQ) s = fmaf(xr[(size_t)(m+3)*XZW + e], w0, s);
    }
    s += cb[e];
    float sig = 1.f / (1.f + __expf(-s));
    g_xc[dir][i] = s * sig;
}

// ---------------- xproj: dbl[M,62] = xc[M,944] * W[62,944]^T ----------------
__global__ __launch_bounds__(256)
void gemm_xproj(const float* __restrict__ A, const float* __restrict__ W,
                float* __restrict__ C)
{
    __shared__ float As[16][68];
    __shared__ float Ws[64][68];
    const int tid = threadIdx.x;
    const int bm  = blockIdx.x * 16;
    const int m   = tid & 15;
    const int nb  = tid >> 4;          // 0..15
    float acc[4] = {0.f, 0.f, 0.f, 0.f};

    for (int k0 = 0; k0 < ED; k0 += 64) {
        {
            int row = tid >> 4;
            int c   = (tid & 15) << 2;
            int k   = k0 + c;
            float4 v = ld4_guard(A + (size_t)(bm+row)*ED + k, k, ED);
            As[row][c+0] = v.x; As[row][c+1] = v.y; As[row][c+2] = v.z; As[row][c+3] = v.w;
        }
#pragma unroll
        for (int i = 0; i < 16; i++) {
            int lin = i*256 + tid;     // 0..4095
            int n = lin >> 6, k = lin & 63;
            float v = 0.f;
            if (n < DBLW && (k0 + k) < ED) v = W[(size_t)n*ED + k0 + k];
            Ws[n][k] = v;
        }
        __syncthreads();
#pragma unroll
        for (int k = 0; k < 64; k++) {
            float a = As[m][k];
            acc[0] = fmaf(a, Ws[nb     ][k], acc[0]);
            acc[1] = fmaf(a, Ws[nb + 16][k], acc[1]);
            acc[2] = fmaf(a, Ws[nb + 32][k], acc[2]);
            acc[3] = fmaf(a, Ws[nb + 48][k], acc[3]);
        }
        __syncthreads();
    }
#pragma unroll
    for (int j = 0; j < 4; j++) {
        int n = nb + 16*j;
        if (n < DBLW) C[(size_t)(bm+m)*DBLW + n] = acc[j];
    }
}

// ---------------- dt: delta[M,944] = softplus(dbl[:, :30]*Wd^T + b) ----------------
__global__ __launch_bounds__(256)
void gemm_dt(const float* __restrict__ dbl, const float* __restrict__ Wd,
             const float* __restrict__ dtb, float* __restrict__ delta)
{
    __shared__ float As[64][33];
    __shared__ float Ws[128][33];
    const int tid = threadIdx.x;
    const int bm  = blockIdx.y * 64;
    const int bn  = blockIdx.x * 128;
#pragma unroll
    for (int i = 0; i < 8; i++) {
        int lin = i*256 + tid;         // 0..2047
        int r = lin >> 5, k = lin & 31;
        As[r][k] = (k < RK) ? dbl[(size_t)(bm+r)*DBLW + k] : 0.f;
    }
#pragma unroll
    for (int i = 0; i < 16; i++) {
        int lin = i*256 + tid;         // 0..4095
        int n = lin >> 5, k = lin & 31;
        int gn = bn + n;
        float v = 0.f;
        if (k < RK && gn < ED) v = Wd[(size_t)gn*RK + k];
        Ws[n][k] = v;
    }
    __syncthreads();
    const int ty = tid >> 5;   // 0..7 -> 8 rows
    const int tx = tid & 31;   //       4 cols
    float acc[8][4];
#pragma unroll
    for (int i = 0; i < 8; i++)
#pragma unroll
        for (int j = 0; j < 4; j++) acc[i][j] = 0.f;
#pragma unroll
    for (int k = 0; k < RK; k++) {
        float a[8], w[4];
#pragma unroll
        for (int i = 0; i < 8; i++) a[i] = As[ty*8+i][k];
#pragma unroll
        for (int j = 0; j < 4; j++) w[j] = Ws[tx*4+j][k];
#pragma unroll
        for (int i = 0; i < 8; i++)
#pragma unroll
            for (int j = 0; j < 4; j++) acc[i][j] = fmaf(a[i], w[j], acc[i][j]);
    }
#pragma unroll
    for (int i = 0; i < 8; i++) {
        size_t row = (size_t)(bm + ty*8 + i);
#pragma unroll
        for (int j = 0; j < 4; j++) {
            int n = bn + tx*4 + j;
            if (n < ED) {
                float v  = acc[i][j] + dtb[n];
                float sp = fmaxf(v, 0.f) + log1pf(__expf(-fabsf(v)));
                delta[row*ED + n] = sp;
            }
        }
    }
}

// ---------------- selective scan (lane-per-state; 16 lanes per channel) ----------------
__global__ __launch_bounds__(256)
void scan_kernel(const float* __restrict__ delta, const float* __restrict__ xc,
                 const float* __restrict__ dbl,  const float* __restrict__ Alog,
                 const float* __restrict__ Dp, int dir, int addmode)
{
    int w    = blockIdx.x * 8 + (threadIdx.x >> 5);   // 0..943
    int lane = threadIdx.x & 31;
    int half = lane >> 4;
    int n    = lane & 15;
    int c    = w*2 + half;           // channel 0..1887
    int b    = c / ED;
    int e    = c - b*ED;
    float An  = -__expf(Alog[e*NST + n]);
    float An2 = An * 1.4426950408889634f;  // * log2(e)
    float Dv  = Dp[e];
    float h = 0.f;
    const float* zp = g_xz + ED;     // z = cols [ED, 2ED)
    for (int tt = 0; tt < LSEQ; tt++) {
        int t = dir ? (LSEQ-1-tt) : tt;
        size_t m = (size_t)b*LSEQ + t;
        float dlt = delta[m*ED + e];
        float xv  = xc[m*ED + e];
        float Bn  = dbl[m*DBLW + RK + n];
        float Cn  = dbl[m*DBLW + RK + NST + n];
        float dA  = exp2f(dlt * An2);
        float u   = dlt * xv * Bn;
        h = fmaf(dA, h, u);
        float p = h * Cn;
        p += __shfl_xor_sync(0xffffffffu, p, 8, 16);
        p += __shfl_xor_sync(0xffffffffu, p, 4, 16);
        p += __shfl_xor_sync(0xffffffffu, p, 2, 16);
        p += __shfl_xor_sync(0xffffffffu, p, 1, 16);
        if (n == 0) {
            float zv = zp[m*XZW + e];
            float sz = zv / (1.f + __expf(-zv));
            float yv = (p + Dv*xv) * sz;
            float* yo = &g_y[m*ED + e];
            if (addmode) *yo += yv; else *yo = yv;
        }
    }
}

// ---------------- host orchestration ----------------
struct BlkP { const float *ip, *cw, *cb, *xp, *dw, *db, *al, *dd, *op; };

static void run_block_host(const BlkP& p, bool bidir,
                           float* hbuf, float* xzbuf,
                           float* xc0, float* xc1,
                           float* dbl0, float* dbl1,
                           float* de0, float* de1, float* ybuf)
{
    // xz = h @ inproj^T   (shared by both directions: inproj(flip(x)) = flip(xz))
    sgemm_nt<<<dim3(15, 32), 256>>>(hbuf, p.ip, xzbuf, XZW, DIMV, 0);
    // depthwise conv + SiLU (fwd, and anticausal for the reverse direction)
    conv_silu_kernel<<<dim3((MROWS*ED + 255)/256, bidir ? 2 : 1), 256>>>(p.cw, p.cb);
    // forward direction
    gemm_xproj<<<MROWS/16, 256>>>(xc0, p.xp, dbl0);
    gemm_dt<<<dim3(8, MROWS/64), 256>>>(dbl0, p.dw, p.db, de0);
    scan_kernel<<<118, 256>>>(de0, xc0, dbl0, p.al, p.dd, 0, 0);
    if (bidir) {
        gemm_xproj<<<MROWS/16, 256>>>(xc1, p.xp, dbl1);
        gemm_dt<<<dim3(8, MROWS/64), 256>>>(dbl1, p.dw, p.db, de1);
        scan_kernel<<<118, 256>>>(de1, xc1, dbl1, p.al, p.dd, 1, 1);
    }
    // h += (y_fwd [+ y_bwd]) @ outproj^T  (single GEMM for both directions)
    sgemm_nt<<<dim3(4, 32), 256>>>(ybuf, p.op, hbuf, DIMV, ED, 1);
}

extern "C" void kernel_launch(void* const* d_in, const int* in_sizes, int n_in,
                              void* d_out, int out_size)
{
    const float* x   = (const float*)d_in[0];
    const float* pw  = (const float*)d_in[1];
    const float* pb  = (const float*)d_in[2];
    const float* lmw = (const float*)d_in[3];
    const float* P[3][9];
    for (int g = 0; g < 3; g++)
        for (int i = 0; i < 9; i++)
            P[g][i] = (const float*)d_in[4 + g*9 + i];

    float *hbuf, *xzbuf, *xcb, *dblb, *deb, *ybuf;
    cudaGetSymbolAddress((void**)&hbuf,  g_h);
    cudaGetSymbolAddress((void**)&xzbuf, g_xz);
    cudaGetSymbolAddress((void**)&xcb,   g_xc);
    cudaGetSymbolAddress((void**)&dblb,  g_dbl);
    cudaGetSymbolAddress((void**)&deb,   g_delta);
    cudaGetSymbolAddress((void**)&ybuf,  g_y);
    float* xc0  = xcb;
    float* xc1  = xcb  + (size_t)MROWS*ED;
    float* dbl0 = dblb;
    float* dbl1 = dblb + (size_t)MROWS*DBLW;
    float* de0  = deb;
    float* de1  = deb  + (size_t)MROWS*ED;

    // 1) patch embed -> h
    patch_kernel<<<(MROWS*DIMV + 255)/256, 256>>>(x, pw, pb);

    // 2) input bidir block: h = h + block(h) + flip(block(flip(h)))
    {
        BlkP p = { P[0][0], P[0][1], P[0][2], P[0][3], P[0][4], P[0][5], P[0][6], P[0][7], P[0][8] };
        run_block_host(p, true, hbuf, xzbuf, xc0, xc1, dbl0, dbl1, de0, de1, ybuf);
    }

    // 3) 8 stacked unidirectional layers: h = h + block(h)
    for (int l = 0; l < NDEPTH; l++) {
        BlkP p = {
            P[1][0] + (size_t)l*XZW*DIMV,
            P[1][1] + (size_t)l*ED*4,
            P[1][2] + (size_t)l*ED,
            P[1][3] + (size_t)l*DBLW*ED,
            P[1][4] + (size_t)l*ED*RK,
            P[1][5] + (size_t)l*ED,
            P[1][6] + (size_t)l*ED*NST,
            P[1][7] + (size_t)l*ED,
            P[1][8] + (size_t)l*DIMV*ED
        };
        run_block_host(p, false, hbuf, xzbuf, xc0, xc1, dbl0, dbl1, de0, de1, ybuf);
    }

    // 4) output bidir block
    {
        BlkP p = { P[2][0], P[2][1], P[2][2], P[2][3], P[2][4], P[2][5], P[2][6], P[2][7], P[2][8] };
        run_block_host(p, true, hbuf, xzbuf, xc0, xc1, dbl0, dbl1, de0, de1, ybuf);
    }

    // 5) lm_head: out = h @ lm_head_w^T
    sgemm_nt<<<dim3(4, 32), 256>>>(hbuf, lmw, (float*)d_out, DIMV, DIMV, 0);
}

// round 7
// speedup vs baseline: 1.1543x; 1.1543x over previous
#include <cuda_runtime.h>
#include <cstdint>
#include <cstddef>

// ---------------- problem constants ----------------
#define BSZ   2
#define LSEQ  2048
#define DIMV  472          // DIM == V
#define ED    944
#define NST   16
#define RK    30
#define NDEPTH 8
#define MROWS (BSZ*LSEQ)   // 4096
#define XZW   (2*ED)       // 1888
#define DBLW  (RK + 2*NST) // 62

// ---------------- scratch (device globals: allocation-free) ----------------
__device__ float g_h[(size_t)MROWS*DIMV];
__device__ float g_xz[(size_t)MROWS*XZW];
__device__ float g_xc[2][(size_t)MROWS*ED];
__device__ float g_dbl[2][(size_t)MROWS*DBLW];
__device__ float g_delta[2][(size_t)MROWS*ED];
__device__ float g_y[2][(size_t)MROWS*ED];

// ---------------- patch embed ----------------
__global__ void patch_kernel(const float* __restrict__ x,
                             const float* __restrict__ pw,
                             const float* __restrict__ pb)
{
    int i = blockIdx.x*blockDim.x + threadIdx.x;
    if (i >= MROWS*DIMV) return;
    int m = i / DIMV, v = i - m*DIMV;
    const float* xr = x + (size_t)m*9;
    const float* wr = pw + (size_t)v*9;
    float s = pb[v];
#pragma unroll
    for (int k = 0; k < 9; k++) s = fmaf(xr[k], wr[k], s);
    g_h[i] = s;
}

__device__ __forceinline__ float4 ld4_guard(const float* p, int k0, int K)
{
    float4 v = make_float4(0.f, 0.f, 0.f, 0.f);
    if (k0 + 3 < K) v = *(const float4*)p;
    else if (k0 < K) {
        v.x = p[0];
        if (k0 + 1 < K) v.y = p[1];
        if (k0 + 2 < K) v.z = p[2];
    }
    return v;
}

// ---------------- tf32-split helpers ----------------
__device__ __forceinline__ uint32_t to_tf32(float a) {
    uint32_t u;
    asm("cvt.rna.tf32.f32 %0, %1;" : "=r"(u) : "f"(a));
    return u;
}
__device__ __forceinline__ void split_tf32(float a, uint32_t& h, uint32_t& l) {
    h = to_tf32(a);
    l = to_tf32(a - __uint_as_float(h));
}

#define MMA_TF32(d, a, b) \
    asm volatile("mma.sync.aligned.m16n8k8.row.col.f32.tf32.tf32.f32 " \
        "{%0,%1,%2,%3}, {%4,%5,%6,%7}, {%8,%9}, {%0,%1,%2,%3};" \
        : "+f"((d)[0]), "+f"((d)[1]), "+f"((d)[2]), "+f"((d)[3]) \
        : "r"((a)[0]), "r"((a)[1]), "r"((a)[2]), "r"((a)[3]), \
          "r"((b)[0]), "r"((b)[1]))

// ---------------- tensor GEMM via mma.sync (tf32 3-pass split) -------------
// C[M,N] = (A(+A2))[M,K] * W[N,K]^T (+C).  M multiple of 128; N,K guarded.
// CTA tile 128x128, K chunk 16.  8 warps: warp tile 32 (m) x 64 (n).
#define TGKC 16
#define SAS  20   // smem row stride in floats (16 + 4 pad): conflict-free frag loads

__global__ __launch_bounds__(256, 1)
void tgemm(const float* __restrict__ A, const float* __restrict__ A2,
           const float* __restrict__ W, float* __restrict__ C,
           int N, int K, int accum)
{
    __shared__ float Ah[128*SAS];
    __shared__ float Al[128*SAS];
    __shared__ float Bh[128*SAS];
    __shared__ float Bl[128*SAS];

    const int tid = threadIdx.x;
    const int bm  = blockIdx.y * 128;
    const int bn  = blockIdx.x * 128;
    const int lr  = tid >> 1;              // 0..127 (row of A/B tile)
    const int lc  = (tid & 1) * 8;         // 0 or 8 (k offset)
    const int nck = (K + TGKC - 1) / TGKC;

    const int lane = tid & 31, wid = tid >> 5;
    const int g = lane >> 2, t = lane & 3;
    const int wm = (wid >> 1) * 32;        // warp row base within tile
    const int wn = (wid & 1)  * 64;        // warp col base within tile

    const float* arow  = A + (size_t)(bm + lr) * K;
    const float* a2row = A2 ? A2 + (size_t)(bm + lr) * K : (const float*)0;
    const bool   wv    = (bn + lr) < N;
    const float* wrow  = W + (size_t)(bn + lr) * K;

    float acc[2][8][4];
#pragma unroll
    for (int mt = 0; mt < 2; mt++)
#pragma unroll
        for (int nt = 0; nt < 8; nt++)
#pragma unroll
            for (int q = 0; q < 4; q++) acc[mt][nt][q] = 0.f;

    float4 va[2], vw[2];

    // prologue: load chunk 0 into regs
    {
        int k0 = lc;
#pragma unroll
        for (int i = 0; i < 2; i++) {
            int gk = k0 + i*4;
            va[i] = ld4_guard(arow + gk, gk, K);
            if (a2row) {
                float4 v2 = ld4_guard(a2row + gk, gk, K);
                va[i].x += v2.x; va[i].y += v2.y; va[i].z += v2.z; va[i].w += v2.w;
            }
            vw[i] = wv ? ld4_guard(wrow + gk, gk, K) : make_float4(0.f,0.f,0.f,0.f);
        }
    }

    for (int ck = 0; ck < nck; ck++) {
        // split current regs to smem planes
#pragma unroll
        for (int i = 0; i < 2; i++) {
            int idx = lr*SAS + lc + i*4;
            uint32_t h0,l0,h1,l1,h2,l2,h3,l3;
            split_tf32(va[i].x, h0, l0); split_tf32(va[i].y, h1, l1);
            split_tf32(va[i].z, h2, l2); split_tf32(va[i].w, h3, l3);
            *(uint4*)&Ah[idx] = make_uint4(h0,h1,h2,h3);
            *(uint4*)&Al[idx] = make_uint4(l0,l1,l2,l3);
            split_tf32(vw[i].x, h0, l0); split_tf32(vw[i].y, h1, l1);
            split_tf32(vw[i].z, h2, l2); split_tf32(vw[i].w, h3, l3);
            *(uint4*)&Bh[idx] = make_uint4(h0,h1,h2,h3);
            *(uint4*)&Bl[idx] = make_uint4(l0,l1,l2,l3);
        }
        __syncthreads();

        // prefetch next chunk into regs (overlaps with MMA below)
        if (ck + 1 < nck) {
            int k0 = (ck+1)*TGKC + lc;
#pragma unroll
            for (int i = 0; i < 2; i++) {
                int gk = k0 + i*4;
                va[i] = ld4_guard(arow + gk, gk, K);
                if (a2row) {
                    float4 v2 = ld4_guard(a2row + gk, gk, K);
                    va[i].x += v2.x; va[i].y += v2.y; va[i].z += v2.z; va[i].w += v2.w;
                }
                vw[i] = wv ? ld4_guard(wrow + gk, gk, K) : make_float4(0.f,0.f,0.f,0.f);
            }
        }

        // compute: 2 k8 steps
#pragma unroll
        for (int kk = 0; kk < TGKC; kk += 8) {
            uint32_t ah[2][4], al[2][4];
#pragma unroll
            for (int mt = 0; mt < 2; mt++) {
                int base = (wm + mt*16 + g)*SAS + kk + t;
                ah[mt][0] = __float_as_uint(Ah[base]);
                ah[mt][1] = __float_as_uint(Ah[base + 8*SAS]);
                ah[mt][2] = __float_as_uint(Ah[base + 4]);
                ah[mt][3] = __float_as_uint(Ah[base + 8*SAS + 4]);
                al[mt][0] = __float_as_uint(Al[base]);
                al[mt][1] = __float_as_uint(Al[base + 8*SAS]);
                al[mt][2] = __float_as_uint(Al[base + 4]);
                al[mt][3] = __float_as_uint(Al[base + 8*SAS + 4]);
            }
            uint32_t bh[8][2], bl[8][2];
#pragma unroll
            for (int nt = 0; nt < 8; nt++) {
                int nb = (wn + nt*8 + g)*SAS + kk + t;
                bh[nt][0] = __float_as_uint(Bh[nb]);
                bh[nt][1] = __float_as_uint(Bh[nb + 4]);
                bl[nt][0] = __float_as_uint(Bl[nb]);
                bl[nt][1] = __float_as_uint(Bl[nb + 4]);
            }
#pragma unroll
            for (int mt = 0; mt < 2; mt++)
#pragma unroll
                for (int nt = 0; nt < 8; nt++)
                    MMA_TF32(acc[mt][nt], ah[mt], bh[nt]);
#pragma unroll
            for (int mt = 0; mt < 2; mt++)
#pragma unroll
                for (int nt = 0; nt < 8; nt++)
                    MMA_TF32(acc[mt][nt], ah[mt], bl[nt]);
#pragma unroll
            for (int mt = 0; mt < 2; mt++)
#pragma unroll
                for (int nt = 0; nt < 8; nt++)
                    MMA_TF32(acc[mt][nt], al[mt], bh[nt]);
        }
        __syncthreads();
    }

    // epilogue
#pragma unroll
    for (int mt = 0; mt < 2; mt++) {
        int row0 = bm + wm + mt*16 + g;
#pragma unroll
        for (int half = 0; half < 2; half++) {
            int rowg = row0 + half*8;
            float* crow = C + (size_t)rowg * N;
#pragma unroll
            for (int nt = 0; nt < 8; nt++) {
                int col = bn + wn + nt*8 + t*2;
                float v0 = acc[mt][nt][half*2 + 0];
                float v1 = acc[mt][nt][half*2 + 1];
                if (col + 1 < N) {
                    float2 v = make_float2(v0, v1);
                    if (accum) {
                        float2 o = *(const float2*)&crow[col];
                        v.x += o.x; v.y += o.y;
                    }
                    *(float2*)&crow[col] = v;
                } else if (col < N) {
                    float v = v0;
                    if (accum) v += crow[col];
                    crow[col] = v;
                }
            }
        }
    }
}

// ---------------- depthwise causal/anticausal conv + SiLU ----------------
__global__ void conv_silu_kernel(const float* __restrict__ cw,
                                 const float* __restrict__ cb)
{
    int dir = blockIdx.y;
    int i = blockIdx.x*blockDim.x + threadIdx.x;
    if (i >= MROWS*ED) return;
    int m = i / ED, e = i - m*ED;
    int t = m & (LSEQ-1);
    float w0 = cw[e*4+0], w1 = cw[e*4+1], w2 = cw[e*4+2], w3 = cw[e*4+3];
    const float* xr = g_xz;  // xi = cols [0,ED)
    float s = xr[(size_t)m*XZW + e] * w3;
    if (dir == 0) {
        if (t >= 1) s = fmaf(xr[(size_t)(m-1)*XZW + e], w2, s);
        if (t >= 2) s = fmaf(xr[(size_t)(m-2)*XZW + e], w1, s);
        if (t >= 3) s = fmaf(xr[(size_t)(m-3)*XZW + e], w0, s);
    } else {
        if (t+1 < LSEQ) s = fmaf(xr[(size_t)(m+1)*XZW + e], w2, s);
        if (t+2 < LSEQ) s = fmaf(xr[(size_t)(m+2)*XZW + e], w1, s);
        if (t+3 < LSEQ) s = fmaf(xr[(size_t)(m+3)*XZW + e], w0, s);
    }
    s += cb[e];
    float sig = 1.f / (1.f + __expf(-s));
    g_xc[dir][i] = s * sig;
}

// ---------------- xproj: dbl[M,62] = xc[M,944] * W[62,944]^T ----------------
__global__ __launch_bounds__(256)
void gemm_xproj(const float* __restrict__ A0, const float* __restrict__ W,
                float* __restrict__ C0)
{
    const float* A = A0 + (size_t)blockIdx.y * MROWS * ED;
    float*       C = C0 + (size_t)blockIdx.y * MROWS * DBLW;
    __shared__ float As[16][68];
    __shared__ float Ws[64][68];
    const int tid = threadIdx.x;
    const int bm  = blockIdx.x * 16;
    const int m   = tid & 15;
    const int nb  = tid >> 4;
    float acc[4] = {0.f, 0.f, 0.f, 0.f};

    for (int k0 = 0; k0 < ED; k0 += 64) {
        {
            int row = tid >> 4;
            int c   = (tid & 15) << 2;
            int k   = k0 + c;
            float4 v = ld4_guard(A + (size_t)(bm+row)*ED + k, k, ED);
            As[row][c+0] = v.x; As[row][c+1] = v.y; As[row][c+2] = v.z; As[row][c+3] = v.w;
        }
#pragma unroll
        for (int i = 0; i < 16; i++) {
            int lin = i*256 + tid;
            int n = lin >> 6, k = lin & 63;
            float v = 0.f;
            if (n < DBLW && (k0 + k) < ED) v = W[(size_t)n*ED + k0 + k];
            Ws[n][k] = v;
        }
        __syncthreads();
#pragma unroll
        for (int k = 0; k < 64; k++) {
            float a = As[m][k];
            acc[0] = fmaf(a, Ws[nb     ][k], acc[0]);
            acc[1] = fmaf(a, Ws[nb + 16][k], acc[1]);
            acc[2] = fmaf(a, Ws[nb + 32][k], acc[2]);
            acc[3] = fmaf(a, Ws[nb + 48][k], acc[3]);
        }
        __syncthreads();
    }
#pragma unroll
    for (int j = 0; j < 4; j++) {
        int n = nb + 16*j;
        if (n < DBLW) C[(size_t)(bm+m)*DBLW + n] = acc[j];
    }
}

// ---------------- dt: delta[M,944] = softplus(dbl[:, :30]*Wd^T + b) ---------
__global__ __launch_bounds__(256)
void gemm_dt(const float* __restrict__ dbl0, const float* __restrict__ Wd,
             const float* __restrict__ dtb, float* __restrict__ delta0)
{
    const float* dbl   = dbl0   + (size_t)blockIdx.z * MROWS * DBLW;
    float*       delta = delta0 + (size_t)blockIdx.z * MROWS * ED;
    __shared__ float As[64][33];
    __shared__ float Ws[128][33];
    const int tid = threadIdx.x;
    const int bm  = blockIdx.y * 64;
    const int bn  = blockIdx.x * 128;
#pragma unroll
    for (int i = 0; i < 8; i++) {
        int lin = i*256 + tid;
        int r = lin >> 5, k = lin & 31;
        As[r][k] = (k < RK) ? dbl[(size_t)(bm+r)*DBLW + k] : 0.f;
    }
#pragma unroll
    for (int i = 0; i < 16; i++) {
        int lin = i*256 + tid;
        int n = lin >> 5, k = lin & 31;
        int gn = bn + n;
        float v = 0.f;
        if (k < RK && gn < ED) v = Wd[(size_t)gn*RK + k];
        Ws[n][k] = v;
    }
    __syncthreads();
    const int ty = tid >> 5;
    const int tx = tid & 31;
    float acc[8][4];
#pragma unroll
    for (int i = 0; i < 8; i++)
#pragma unroll
        for (int j = 0; j < 4; j++) acc[i][j] = 0.f;
#pragma unroll
    for (int k = 0; k < RK; k++) {
        float a[8], w[4];
#pragma unroll
        for (int i = 0; i < 8; i++) a[i] = As[ty*8+i][k];
#pragma unroll
        for (int j = 0; j < 4; j++) w[j] = Ws[tx*4+j][k];
#pragma unroll
        for (int i = 0; i < 8; i++)
#pragma unroll
            for (int j = 0; j < 4; j++) acc[i][j] = fmaf(a[i], w[j], acc[i][j]);
    }
#pragma unroll
    for (int i = 0; i < 8; i++) {
        size_t row = (size_t)(bm + ty*8 + i);
#pragma unroll
        for (int j = 0; j < 4; j++) {
            int n = bn + tx*4 + j;
            if (n < ED) {
                float v  = acc[i][j] + dtb[n];
                float sp = fmaxf(v, 0.f) + log1pf(__expf(-fabsf(v)));
                delta[row*ED + n] = sp;
            }
        }
    }
}

// ---------------- selective scan (dir from blockIdx.y) ----------------
__global__ __launch_bounds__(256)
void scan_kernel(const float* __restrict__ delta0, const float* __restrict__ xc0,
                 const float* __restrict__ dbl0,  const float* __restrict__ Alog,
                 const float* __restrict__ Dp)
{
    int dir = blockIdx.y;
    const float* delta = delta0 + (size_t)dir * MROWS * ED;
    const float* xc    = xc0    + (size_t)dir * MROWS * ED;
    const float* dbl   = dbl0   + (size_t)dir * MROWS * DBLW;
    float*       yout  = &g_y[dir][0];

    int w    = blockIdx.x * 8 + (threadIdx.x >> 5);   // 0..943
    int lane = threadIdx.x & 31;
    int half = lane >> 4;
    int n    = lane & 15;
    int c    = w*2 + half;
    int b    = c / ED;
    int e    = c - b*ED;
    float An  = -__expf(Alog[e*NST + n]);
    float An2 = An * 1.4426950408889634f;
    float Dv  = Dp[e];
    float h = 0.f;
    const float* zp = g_xz + ED;
#pragma unroll 2
    for (int tt = 0; tt < LSEQ; tt++) {
        int t = dir ? (LSEQ-1-tt) : tt;
        size_t m = (size_t)b*LSEQ + t;
        float dlt = delta[m*ED + e];
        float xv  = xc[m*ED + e];
        float Bn  = dbl[m*DBLW + RK + n];
        float Cn  = dbl[m*DBLW + RK + NST + n];
        float dA  = exp2f(dlt * An2);
        float u   = dlt * xv * Bn;
        h = fmaf(dA, h, u);
        float p = h * Cn;
        p += __shfl_xor_sync(0xffffffffu, p, 8, 16);
        p += __shfl_xor_sync(0xffffffffu, p, 4, 16);
        p += __shfl_xor_sync(0xffffffffu, p, 2, 16);
        p += __shfl_xor_sync(0xffffffffu, p, 1, 16);
        if (n == 0) {
            float zv = zp[m*XZW + e];
            float sz = zv / (1.f + __expf(-zv));
            yout[m*ED + e] = (p + Dv*xv) * sz;
        }
    }
}

// ---------------- host orchestration ----------------
struct BlkP { const float *ip, *cw, *cb, *xp, *dw, *db, *al, *dd, *op; };

static void run_block_host(const BlkP& p, bool bidir,
                           float* hbuf, float* xzbuf,
                           float* xc0, float* dbl0, float* de0,
                           float* y0, float* y1)
{
    int ndir = bidir ? 2 : 1;
    // xz = h @ inproj^T (shared: inproj(flip(x)) = flip(xz))
    tgemm<<<dim3(15, 32), 256>>>(hbuf, nullptr, p.ip, xzbuf, XZW, DIMV, 0);
    conv_silu_kernel<<<dim3((MROWS*ED + 255)/256, ndir), 256>>>(p.cw, p.cb);
    gemm_xproj<<<dim3(MROWS/16, ndir), 256>>>(xc0, p.xp, dbl0);
    gemm_dt<<<dim3(8, MROWS/64, ndir), 256>>>(dbl0, p.dw, p.db, de0);
    scan_kernel<<<dim3(118, ndir), 256>>>(de0, xc0, dbl0, p.al, p.dd);
    // h += (y0 [+ y1]) @ outproj^T
    tgemm<<<dim3(4, 32), 256>>>(y0, bidir ? y1 : nullptr, p.op, hbuf, DIMV, ED, 1);
}

extern "C" void kernel_launch(void* const* d_in, const int* in_sizes, int n_in,
                              void* d_out, int out_size)
{
    const float* x   = (const float*)d_in[0];
    const float* pw  = (const float*)d_in[1];
    const float* pb  = (const float*)d_in[2];
    const float* lmw = (const float*)d_in[3];
    const float* P[3][9];
    for (int g = 0; g < 3; g++)
        for (int i = 0; i < 9; i++)
            P[g][i] = (const float*)d_in[4 + g*9 + i];

    float *hbuf, *xzbuf, *xcb, *dblb, *deb, *ybuf;
    cudaGetSymbolAddress((void**)&hbuf,  g_h);
    cudaGetSymbolAddress((void**)&xzbuf, g_xz);
    cudaGetSymbolAddress((void**)&xcb,   g_xc);
    cudaGetSymbolAddress((void**)&dblb,  g_dbl);
    cudaGetSymbolAddress((void**)&deb,   g_delta);
    cudaGetSymbolAddress((void**)&ybuf,  g_y);
    float* y0 = ybuf;
    float* y1 = ybuf + (size_t)MROWS*ED;

    patch_kernel<<<(MROWS*DIMV + 255)/256, 256>>>(x, pw, pb);

    {
        BlkP p = { P[0][0], P[0][1], P[0][2], P[0][3], P[0][4], P[0][5], P[0][6], P[0][7], P[0][8] };
        run_block_host(p, true, hbuf, xzbuf, xcb, dblb, deb, y0, y1);
    }
    for (int l = 0; l < NDEPTH; l++) {
        BlkP p = {
            P[1][0] + (size_t)l*XZW*DIMV,
            P[1][1] + (size_t)l*ED*4,
            P[1][2] + (size_t)l*ED,
            P[1][3] + (size_t)l*DBLW*ED,
            P[1][4] + (size_t)l*ED*RK,
            P[1][5] + (size_t)l*ED,
            P[1][6] + (size_t)l*ED*NST,
            P[1][7] + (size_t)l*ED,
            P[1][8] + (size_t)l*DIMV*ED
        };
        run_block_host(p, false, hbuf, xzbuf, xcb, dblb, deb, y0, y1);
    }
    {
        BlkP p = { P[2][0], P[2][1], P[2][2], P[2][3], P[2][4], P[2][5], P[2][6], P[2][7], P[2][8] };
        run_block_host(p, true, hbuf, xzbuf, xcb, dblb, deb, y0, y1);
    }

    tgemm<<<dim3(4, 32), 256>>>(hbuf, nullptr, lmw, (float*)d_out, DIMV, DIMV, 0);
}

// round 8
// speedup vs baseline: 2.9259x; 2.5348x over previous
#include <cuda_runtime.h>
#include <cstdint>
#include <cstddef>

// ---------------- problem constants ----------------
#define BSZ   2
#define LSEQ  2048
#define DIMV  472          // DIM == V
#define ED    944
#define NST   16
#define RK    30
#define NDEPTH 8
#define MROWS (BSZ*LSEQ)   // 4096
#define XZW   (2*ED)       // 1888
#define DBLW  (RK + 2*NST) // 62

// scan chunking: 16 chunks of 128 steps, one warp per chunk
#define SCH   16
#define SCL   (LSEQ/SCH)   // 128

// ---------------- scratch (device globals: allocation-free) ----------------
__device__ float g_h[(size_t)MROWS*DIMV];
__device__ float g_xz[(size_t)MROWS*XZW];
__device__ float g_xc[2][(size_t)MROWS*ED];
__device__ float g_dbl[2][(size_t)MROWS*DBLW];
__device__ float g_delta[2][(size_t)MROWS*ED];
__device__ float g_y[2][(size_t)MROWS*ED];

// ---------------- patch embed ----------------
__global__ void patch_kernel(const float* __restrict__ x,
                             const float* __restrict__ pw,
                             const float* __restrict__ pb)
{
    int i = blockIdx.x*blockDim.x + threadIdx.x;
    if (i >= MROWS*DIMV) return;
    int m = i / DIMV, v = i - m*DIMV;
    const float* xr = x + (size_t)m*9;
    const float* wr = pw + (size_t)v*9;
    float s = pb[v];
#pragma unroll
    for (int k = 0; k < 9; k++) s = fmaf(xr[k], wr[k], s);
    g_h[i] = s;
}

__device__ __forceinline__ float4 ld4_guard(const float* p, int k0, int K)
{
    float4 v = make_float4(0.f, 0.f, 0.f, 0.f);
    if (k0 + 3 < K) v = *(const float4*)p;
    else if (k0 < K) {
        v.x = p[0];
        if (k0 + 1 < K) v.y = p[1];
        if (k0 + 2 < K) v.z = p[2];
    }
    return v;
}

// ---------------- tf32-split helpers ----------------
__device__ __forceinline__ uint32_t to_tf32(float a) {
    uint32_t u;
    asm("cvt.rna.tf32.f32 %0, %1;" : "=r"(u) : "f"(a));
    return u;
}
__device__ __forceinline__ void split_tf32(float a, uint32_t& h, uint32_t& l) {
    h = to_tf32(a);
    l = to_tf32(a - __uint_as_float(h));
}

#define MMA_TF32(d, a, b) \
    asm volatile("mma.sync.aligned.m16n8k8.row.col.f32.tf32.tf32.f32 " \
        "{%0,%1,%2,%3}, {%4,%5,%6,%7}, {%8,%9}, {%0,%1,%2,%3};" \
        : "+f"((d)[0]), "+f"((d)[1]), "+f"((d)[2]), "+f"((d)[3]) \
        : "r"((a)[0]), "r"((a)[1]), "r"((a)[2]), "r"((a)[3]), \
          "r"((b)[0]), "r"((b)[1]))

// ---------------- tensor GEMM via mma.sync (tf32 3-pass split) -------------
// C[M,N] = (A(+A2))[M,K] * W[N,K]^T (+C).  M multiple of 128; N,K guarded.
// CTA tile 128x128, K chunk 16.  8 warps: warp tile 32 (m) x 64 (n).
#define TGKC 16
#define SAS  20   // smem row stride in floats (16 + 4 pad): conflict-free frag loads

__global__ __launch_bounds__(256, 1)
void tgemm(const float* __restrict__ A, const float* __restrict__ A2,
           const float* __restrict__ W, float* __restrict__ C,
           int N, int K, int accum)
{
    __shared__ float Ah[128*SAS];
    __shared__ float Al[128*SAS];
    __shared__ float Bh[128*SAS];
    __shared__ float Bl[128*SAS];

    const int tid = threadIdx.x;
    const int bm  = blockIdx.y * 128;
    const int bn  = blockIdx.x * 128;
    const int lr  = tid >> 1;              // 0..127 (row of A/B tile)
    const int lc  = (tid & 1) * 8;         // 0 or 8 (k offset)
    const int nck = (K + TGKC - 1) / TGKC;

    const int lane = tid & 31, wid = tid >> 5;
    const int g = lane >> 2, t = lane & 3;
    const int wm = (wid >> 1) * 32;        // warp row base within tile
    const int wn = (wid & 1)  * 64;        // warp col base within tile

    const float* arow  = A + (size_t)(bm + lr) * K;
    const float* a2row = A2 ? A2 + (size_t)(bm + lr) * K : (const float*)0;
    const bool   wv    = (bn + lr) < N;
    const float* wrow  = W + (size_t)(bn + lr) * K;

    float acc[2][8][4];
#pragma unroll
    for (int mt = 0; mt < 2; mt++)
#pragma unroll
        for (int nt = 0; nt < 8; nt++)
#pragma unroll
            for (int q = 0; q < 4; q++) acc[mt][nt][q] = 0.f;

    float4 va[2], vw[2];

    // prologue: load chunk 0 into regs
    {
        int k0 = lc;
#pragma unroll
        for (int i = 0; i < 2; i++) {
            int gk = k0 + i*4;
            va[i] = ld4_guard(arow + gk, gk, K);
            if (a2row) {
                float4 v2 = ld4_guard(a2row + gk, gk, K);
                va[i].x += v2.x; va[i].y += v2.y; va[i].z += v2.z; va[i].w += v2.w;
            }
            vw[i] = wv ? ld4_guard(wrow + gk, gk, K) : make_float4(0.f,0.f,0.f,0.f);
        }
    }

    for (int ck = 0; ck < nck; ck++) {
        // split current regs to smem planes
#pragma unroll
        for (int i = 0; i < 2; i++) {
            int idx = lr*SAS + lc + i*4;
            uint32_t h0,l0,h1,l1,h2,l2,h3,l3;
            split_tf32(va[i].x, h0, l0); split_tf32(va[i].y, h1, l1);
            split_tf32(va[i].z, h2, l2); split_tf32(va[i].w, h3, l3);
            *(uint4*)&Ah[idx] = make_uint4(h0,h1,h2,h3);
            *(uint4*)&Al[idx] = make_uint4(l0,l1,l2,l3);
            split_tf32(vw[i].x, h0, l0); split_tf32(vw[i].y, h1, l1);
            split_tf32(vw[i].z, h2, l2); split_tf32(vw[i].w, h3, l3);
            *(uint4*)&Bh[idx] = make_uint4(h0,h1,h2,h3);
            *(uint4*)&Bl[idx] = make_uint4(l0,l1,l2,l3);
        }
        __syncthreads();

        // prefetch next chunk into regs (overlaps with MMA below)
        if (ck + 1 < nck) {
            int k0 = (ck+1)*TGKC + lc;
#pragma unroll
            for (int i = 0; i < 2; i++) {
                int gk = k0 + i*4;
                va[i] = ld4_guard(arow + gk, gk, K);
                if (a2row) {
                    float4 v2 = ld4_guard(a2row + gk, gk, K);
                    va[i].x += v2.x; va[i].y += v2.y; va[i].z += v2.z; va[i].w += v2.w;
                }
                vw[i] = wv ? ld4_guard(wrow + gk, gk, K) : make_float4(0.f,0.f,0.f,0.f);
            }
        }

        // compute: 2 k8 steps
#pragma unroll
        for (int kk = 0; kk < TGKC; kk += 8) {
            uint32_t ah[2][4], al[2][4];
#pragma unroll
            for (int mt = 0; mt < 2; mt++) {
                int base = (wm + mt*16 + g)*SAS + kk + t;
                ah[mt][0] = __float_as_uint(Ah[base]);
                ah[mt][1] = __float_as_uint(Ah[base + 8*SAS]);
                ah[mt][2] = __float_as_uint(Ah[base + 4]);
                ah[mt][3] = __float_as_uint(Ah[base + 8*SAS + 4]);
                al[mt][0] = __float_as_uint(Al[base]);
                al[mt][1] = __float_as_uint(Al[base + 8*SAS]);
                al[mt][2] = __float_as_uint(Al[base + 4]);
                al[mt][3] = __float_as_uint(Al[base + 8*SAS + 4]);
            }
            uint32_t bh[8][2], bl[8][2];
#pragma unroll
            for (int nt = 0; nt < 8; nt++) {
                int nb = (wn + nt*8 + g)*SAS + kk + t;
                bh[nt][0] = __float_as_uint(Bh[nb]);
                bh[nt][1] = __float_as_uint(Bh[nb + 4]);
                bl[nt][0] = __float_as_uint(Bl[nb]);
                bl[nt][1] = __float_as_uint(Bl[nb + 4]);
            }
#pragma unroll
            for (int mt = 0; mt < 2; mt++)
#pragma unroll
                for (int nt = 0; nt < 8; nt++)
                    MMA_TF32(acc[mt][nt], ah[mt], bh[nt]);
#pragma unroll
            for (int mt = 0; mt < 2; mt++)
#pragma unroll
                for (int nt = 0; nt < 8; nt++)
                    MMA_TF32(acc[mt][nt], ah[mt], bl[nt]);
#pragma unroll
            for (int mt = 0; mt < 2; mt++)
#pragma unroll
                for (int nt = 0; nt < 8; nt++)
                    MMA_TF32(acc[mt][nt], al[mt], bh[nt]);
        }
        __syncthreads();
    }

    // epilogue
#pragma unroll
    for (int mt = 0; mt < 2; mt++) {
        int row0 = bm + wm + mt*16 + g;
#pragma unroll
        for (int half = 0; half < 2; half++) {
            int rowg = row0 + half*8;
            float* crow = C + (size_t)rowg * N;
#pragma unroll
            for (int nt = 0; nt < 8; nt++) {
                int col = bn + wn + nt*8 + t*2;
                float v0 = acc[mt][nt][half*2 + 0];
                float v1 = acc[mt][nt][half*2 + 1];
                if (col + 1 < N) {
                    float2 v = make_float2(v0, v1);
                    if (accum) {
                        float2 o = *(const float2*)&crow[col];
                        v.x += o.x; v.y += o.y;
                    }
                    *(float2*)&crow[col] = v;
                } else if (col < N) {
                    float v = v0;
                    if (accum) v += crow[col];
                    crow[col] = v;
                }
            }
        }
    }
}

// ---------------- depthwise causal/anticausal conv + SiLU ----------------
__global__ void conv_silu_kernel(const float* __restrict__ cw,
                                 const float* __restrict__ cb)
{
    int dir = blockIdx.y;
    int i = blockIdx.x*blockDim.x + threadIdx.x;
    if (i >= MROWS*ED) return;
    int m = i / ED, e = i - m*ED;
    int t = m & (LSEQ-1);
    float w0 = cw[e*4+0], w1 = cw[e*4+1], w2 = cw[e*4+2], w3 = cw[e*4+3];
    const float* xr = g_xz;  // xi = cols [0,ED)
    float s = xr[(size_t)m*XZW + e] * w3;
    if (dir == 0) {
        if (t >= 1) s = fmaf(xr[(size_t)(m-1)*XZW + e], w2, s);
        if (t >= 2) s = fmaf(xr[(size_t)(m-2)*XZW + e], w1, s);
        if (t >= 3) s = fmaf(xr[(size_t)(m-3)*XZW + e], w0, s);
    } else {
        if (t+1 < LSEQ) s = fmaf(xr[(size_t)(m+1)*XZW + e], w2, s);
        if (t+2 < LSEQ) s = fmaf(xr[(size_t)(m+2)*XZW + e], w1, s);
        if (t+3 < LSEQ) s = fmaf(xr[(size_t)(m+3)*XZW + e], w0, s);
    }
    s += cb[e];
    float sig = 1.f / (1.f + __expf(-s));
    g_xc[dir][i] = s * sig;
}

// ---------------- xproj: dbl[M,62] = xc[M,944] * W[62,944]^T ----------------
__global__ __launch_bounds__(256)
void gemm_xproj(const float* __restrict__ A0, const float* __restrict__ W,
                float* __restrict__ C0)
{
    const float* A = A0 + (size_t)blockIdx.y * MROWS * ED;
    float*       C = C0 + (size_t)blockIdx.y * MROWS * DBLW;
    __shared__ float As[16][68];
    __shared__ float Ws[64][68];
    const int tid = threadIdx.x;
    const int bm  = blockIdx.x * 16;
    const int m   = tid & 15;
    const int nb  = tid >> 4;
    float acc[4] = {0.f, 0.f, 0.f, 0.f};

    for (int k0 = 0; k0 < ED; k0 += 64) {
        {
            int row = tid >> 4;
            int c   = (tid & 15) << 2;
            int k   = k0 + c;
            float4 v = ld4_guard(A + (size_t)(bm+row)*ED + k, k, ED);
            As[row][c+0] = v.x; As[row][c+1] = v.y; As[row][c+2] = v.z; As[row][c+3] = v.w;
        }
#pragma unroll
        for (int i = 0; i < 16; i++) {
            int lin = i*256 + tid;
            int n = lin >> 6, k = lin & 63;
            float v = 0.f;
            if (n < DBLW && (k0 + k) < ED) v = W[(size_t)n*ED + k0 + k];
            Ws[n][k] = v;
        }
        __syncthreads();
#pragma unroll
        for (int k = 0; k < 64; k++) {
            float a = As[m][k];
            acc[0] = fmaf(a, Ws[nb     ][k], acc[0]);
            acc[1] = fmaf(a, Ws[nb + 16][k], acc[1]);
            acc[2] = fmaf(a, Ws[nb + 32][k], acc[2]);
            acc[3] = fmaf(a, Ws[nb + 48][k], acc[3]);
        }
        __syncthreads();
    }
#pragma unroll
    for (int j = 0; j < 4; j++) {
        int n = nb + 16*j;
        if (n < DBLW) C[(size_t)(bm+m)*DBLW + n] = acc[j];
    }
}

// ---------------- dt: delta[M,944] = softplus(dbl[:, :30]*Wd^T + b) ---------
__global__ __launch_bounds__(256)
void gemm_dt(const float* __restrict__ dbl0, const float* __restrict__ Wd,
             const float* __restrict__ dtb, float* __restrict__ delta0)
{
    const float* dbl   = dbl0   + (size_t)blockIdx.z * MROWS * DBLW;
    float*       delta = delta0 + (size_t)blockIdx.z * MROWS * ED;
    __shared__ float As[64][33];
    __shared__ float Ws[128][33];
    const int tid = threadIdx.x;
    const int bm  = blockIdx.y * 64;
    const int bn  = blockIdx.x * 128;
#pragma unroll
    for (int i = 0; i < 8; i++) {
        int lin = i*256 + tid;
        int r = lin >> 5, k = lin & 31;
        As[r][k] = (k < RK) ? dbl[(size_t)(bm+r)*DBLW + k] : 0.f;
    }
#pragma unroll
    for (int i = 0; i < 16; i++) {
        int lin = i*256 + tid;
        int n = lin >> 5, k = lin & 31;
        int gn = bn + n;
        float v = 0.f;
        if (k < RK && gn < ED) v = Wd[(size_t)gn*RK + k];
        Ws[n][k] = v;
    }
    __syncthreads();
    const int ty = tid >> 5;
    const int tx = tid & 31;
    float acc[8][4];
#pragma unroll
    for (int i = 0; i < 8; i++)
#pragma unroll
        for (int j = 0; j < 4; j++) acc[i][j] = 0.f;
#pragma unroll
    for (int k = 0; k < RK; k++) {
        float a[8], w[4];
#pragma unroll
        for (int i = 0; i < 8; i++) a[i] = As[ty*8+i][k];
#pragma unroll
        for (int j = 0; j < 4; j++) w[j] = Ws[tx*4+j][k];
#pragma unroll
        for (int i = 0; i < 8; i++)
#pragma unroll
            for (int j = 0; j < 4; j++) acc[i][j] = fmaf(a[i], w[j], acc[i][j]);
    }
#pragma unroll
    for (int i = 0; i < 8; i++) {
        size_t row = (size_t)(bm + ty*8 + i);
#pragma unroll
        for (int j = 0; j < 4; j++) {
            int n = bn + tx*4 + j;
            if (n < ED) {
                float v  = acc[i][j] + dtb[n];
                float sp = fmaxf(v, 0.f) + log1pf(__expf(-fabsf(v)));
                delta[row*ED + n] = sp;
            }
        }
    }
}

// ---------------- chunked parallel selective scan ----------------
// block = 512 threads = 16 warps; one block per channel-pair; warp w owns
// time-chunk [w*128, (w+1)*128).  Pass A: local scan from h=0 tracking
// P = prod(dA).  Combine: hin = serial fold of 15 chunk summaries.
// Pass B: replay chunk from hin, produce y.
__global__ __launch_bounds__(512)
void scan_kernel(const float* __restrict__ delta0, const float* __restrict__ xc0,
                 const float* __restrict__ dbl0,  const float* __restrict__ Alog,
                 const float* __restrict__ Dp)
{
    int dir = blockIdx.y;
    const float* delta = delta0 + (size_t)dir * MROWS * ED;
    const float* xc    = xc0    + (size_t)dir * MROWS * ED;
    const float* dbl   = dbl0   + (size_t)dir * MROWS * DBLW;
    float*       yout  = &g_y[dir][0];

    __shared__ float sH[SCH][32];
    __shared__ float sP[SCH][32];

    const int wid  = threadIdx.x >> 5;     // chunk index 0..15
    const int lane = threadIdx.x & 31;
    const int half = lane >> 4;
    const int n    = lane & 15;
    const int c    = blockIdx.x * 2 + half;   // channel 0..1887
    const int b    = c / ED;
    const int e    = c - b*ED;

    const float An2 = -__expf(Alog[e*NST + n]) * 1.4426950408889634f;
    const float Dv  = Dp[e];
    const float* zp = g_xz + ED;
    const size_t mbase = (size_t)b * LSEQ;
    const int t0 = wid * SCL;

    // ---- pass A: local scan, track product of dA ----
    float h = 0.f, P = 1.f;
#pragma unroll 4
    for (int i = 0; i < SCL; i++) {
        int tt = t0 + i;
        int t  = dir ? (LSEQ-1-tt) : tt;
        size_t m = mbase + t;
        float dlt = delta[m*ED + e];
        float xv  = xc[m*ED + e];
        float Bn  = dbl[m*DBLW + RK + n];
        float dA  = exp2f(dlt * An2);
        h = fmaf(dA, h, dlt * xv * Bn);
        P *= dA;
    }
    sH[wid][lane] = h;
    sP[wid][lane] = P;
    __syncthreads();

    // ---- combine: incoming state for this chunk ----
    float hin = 0.f;
    for (int j = 0; j < wid; j++)
        hin = fmaf(sP[j][lane], hin, sH[j][lane]);

    // ---- pass B: replay chunk from hin, emit y ----
    h = hin;
#pragma unroll 2
    for (int i = 0; i < SCL; i++) {
        int tt = t0 + i;
        int t  = dir ? (LSEQ-1-tt) : tt;
        size_t m = mbase + t;
        float dlt = delta[m*ED + e];
        float xv  = xc[m*ED + e];
        float Bn  = dbl[m*DBLW + RK + n];
        float Cn  = dbl[m*DBLW + RK + NST + n];
        float dA  = exp2f(dlt * An2);
        h = fmaf(dA, h, dlt * xv * Bn);
        float p = h * Cn;
        p += __shfl_xor_sync(0xffffffffu, p, 8, 16);
        p += __shfl_xor_sync(0xffffffffu, p, 4, 16);
        p += __shfl_xor_sync(0xffffffffu, p, 2, 16);
        p += __shfl_xor_sync(0xffffffffu, p, 1, 16);
        if (n == 0) {
            float zv = zp[m*XZW + e];
            float sz = zv / (1.f + __expf(-zv));
            yout[m*ED + e] = (p + Dv*xv) * sz;
        }
    }
}

// ---------------- host orchestration ----------------
struct BlkP { const float *ip, *cw, *cb, *xp, *dw, *db, *al, *dd, *op; };

static void run_block_host(const BlkP& p, bool bidir,
                           float* hbuf, float* xzbuf,
                           float* xc0, float* dbl0, float* de0,
                           float* y0, float* y1)
{
    int ndir = bidir ? 2 : 1;
    // xz = h @ inproj^T (shared: inproj(flip(x)) = flip(xz))
    tgemm<<<dim3(15, 32), 256>>>(hbuf, nullptr, p.ip, xzbuf, XZW, DIMV, 0);
    conv_silu_kernel<<<dim3((MROWS*ED + 255)/256, ndir), 256>>>(p.cw, p.cb);
    gemm_xproj<<<dim3(MROWS/16, ndir), 256>>>(xc0, p.xp, dbl0);
    gemm_dt<<<dim3(8, MROWS/64, ndir), 256>>>(dbl0, p.dw, p.db, de0);
    scan_kernel<<<dim3(944, ndir), 512>>>(de0, xc0, dbl0, p.al, p.dd);
    // h += (y0 [+ y1]) @ outproj^T
    tgemm<<<dim3(4, 32), 256>>>(y0, bidir ? y1 : nullptr, p.op, hbuf, DIMV, ED, 1);
}

extern "C" void kernel_launch(void* const* d_in, const int* in_sizes, int n_in,
                              void* d_out, int out_size)
{
    const float* x   = (const float*)d_in[0];
    const float* pw  = (const float*)d_in[1];
    const float* pb  = (const float*)d_in[2];
    const float* lmw = (const float*)d_in[3];
    const float* P[3][9];
    for (int g = 0; g < 3; g++)
        for (int i = 0; i < 9; i++)
            P[g][i] = (const float*)d_in[4 + g*9 + i];

    float *hbuf, *xzbuf, *xcb, *dblb, *deb, *ybuf;
    cudaGetSymbolAddress((void**)&hbuf,  g_h);
    cudaGetSymbolAddress((void**)&xzbuf, g_xz);
    cudaGetSymbolAddress((void**)&xcb,   g_xc);
    cudaGetSymbolAddress((void**)&dblb,  g_dbl);
    cudaGetSymbolAddress((void**)&deb,   g_delta);
    cudaGetSymbolAddress((void**)&ybuf,  g_y);
    float* y0 = ybuf;
    float* y1 = ybuf + (size_t)MROWS*ED;

    patch_kernel<<<(MROWS*DIMV + 255)/256, 256>>>(x, pw, pb);

    {
        BlkP p = { P[0][0], P[0][1], P[0][2], P[0][3], P[0][4], P[0][5], P[0][6], P[0][7], P[0][8] };
        run_block_host(p, true, hbuf, xzbuf, xcb, dblb, deb, y0, y1);
    }
    for (int l = 0; l < NDEPTH; l++) {
        BlkP p = {
            P[1][0] + (size_t)l*XZW*DIMV,
            P[1][1] + (size_t)l*ED*4,
            P[1][2] + (size_t)l*ED,
            P[1][3] + (size_t)l*DBLW*ED,
            P[1][4] + (size_t)l*ED*RK,
            P[1][5] + (size_t)l*ED,
            P[1][6] + (size_t)l*ED*NST,
            P[1][7] + (size_t)l*ED,
            P[1][8] + (size_t)l*DIMV*ED
        };
        run_block_host(p, false, hbuf, xzbuf, xcb, dblb, deb, y0, y1);
    }
    {
        BlkP p = { P[2][0], P[2][1], P[2][2], P[2][3], P[2][4], P[2][5], P[2][6], P[2][7], P[2][8] };
        run_block_host(p, true, hbuf, xzbuf, xcb, dblb, deb, y0, y1);
    }

    tgemm<<<dim3(4, 32), 256>>>(hbuf, nullptr, lmw, (float*)d_out, DIMV, DIMV, 0);
}